// round 17
// baseline (speedup 1.0000x reference)
#include <cuda_runtime.h>
#include <cuda_fp16.h>
#include <cstdint>
#include <cstddef>

#define HID   4096
#define LQ    128
#define CTXN  896
#define TT    1024
#define STATE 3072
#define HQ    32
#define HKV   8
#define DH    128
#define SCALE 0.08838834764831845f
#define NEPS  1e-6f

// ---------------- scratch (device globals; no allocation APIs) ----------------
__device__ __align__(16) float g_q [LQ * HID];
__device__ __align__(16) float g_k [TT * HKV * DH];
__device__ __align__(16) float g_v [TT * HKV * DH];
__device__ __align__(16) float g_o [LQ * HID];
__device__ __align__(16) float g_ps[4 * LQ * HID];    // split-K partials (2M floats)

// attention split-KV partials
__device__ __align__(16) float g_aO[2 * HQ * LQ * DH];
__device__ __align__(16) float g_aM[2 * HQ * LQ];
__device__ __align__(16) float g_aL[2 * HQ * LQ];

// fp16 operands
__device__ __align__(16) __half c_actH[TT * HID];
__device__ __align__(16) __half c_actL[TT * HID];
__device__ __align__(16) __half c_wq  [HID * HID];
__device__ __align__(16) __half c_wk  [HKV * DH * HID];
__device__ __align__(16) __half c_wv  [HKV * DH * HID];
__device__ __align__(16) __half c_wo  [HID * HID];
__device__ __align__(16) __half c_goH [LQ * HID];
__device__ __align__(16) __half c_goL [LQ * HID];
__device__ __align__(16) __half c_qrH [HQ * LQ * DH];
__device__ __align__(16) __half c_qrL [HQ * LQ * DH];
__device__ __align__(16) __half c_kc  [HKV * 4096 * DH];
__device__ __align__(16) __half c_vc  [HKV * 4096 * DH];

// ---------------- mma helpers ----------------
static __device__ __forceinline__ uint32_t smem_u32(const void* p) {
    uint32_t a;
    asm("{ .reg .u64 t; cvta.to.shared.u64 t, %1; cvt.u32.u64 %0, t; }"
        : "=r"(a) : "l"(p));
    return a;
}
static __device__ __forceinline__ void ldm4(uint32_t* r, uint32_t addr) {
    asm volatile("ldmatrix.sync.aligned.m8n8.x4.shared.b16 {%0,%1,%2,%3}, [%4];"
                 : "=r"(r[0]), "=r"(r[1]), "=r"(r[2]), "=r"(r[3]) : "r"(addr));
}
static __device__ __forceinline__ void ldm4t(uint32_t* r, uint32_t addr) {
    asm volatile("ldmatrix.sync.aligned.m8n8.x4.trans.shared.b16 {%0,%1,%2,%3}, [%4];"
                 : "=r"(r[0]), "=r"(r[1]), "=r"(r[2]), "=r"(r[3]) : "r"(addr));
}
static __device__ __forceinline__ void mma_f16(float* c, const uint32_t* a,
                                               uint32_t b0, uint32_t b1) {
    asm volatile(
        "mma.sync.aligned.m16n8k16.row.col.f32.f16.f16.f32 "
        "{%0,%1,%2,%3}, {%4,%5,%6,%7}, {%8,%9}, {%0,%1,%2,%3};"
        : "+f"(c[0]), "+f"(c[1]), "+f"(c[2]), "+f"(c[3])
        : "r"(a[0]), "r"(a[1]), "r"(a[2]), "r"(a[3]), "r"(b0), "r"(b1));
}
#define CPA16(dst, src) \
    asm volatile("cp.async.cg.shared.global [%0], [%1], 16;" \
                 :: "r"(dst), "l"(src) : "memory")
#define CPA_COMMIT() asm volatile("cp.async.commit_group;" ::: "memory")
#define CPA_WAIT2()  asm volatile("cp.async.wait_group 2;" ::: "memory")
#define CPA_WAIT1G() asm volatile("cp.async.wait_group 1;" ::: "memory")

// ---------------- fp32 -> fp16 split helpers ----------------
static __device__ __forceinline__ void split4h(float4 f, uint2& h, uint2& l) {
    __half2 h01 = __floats2half2_rn(f.x, f.y);
    __half2 h23 = __floats2half2_rn(f.z, f.w);
    float2 r01 = __half22float2(h01);
    float2 r23 = __half22float2(h23);
    __half2 l01 = __floats2half2_rn(f.x - r01.x, f.y - r01.y);
    __half2 l23 = __floats2half2_rn(f.z - r23.x, f.w - r23.y);
    h.x = *(uint32_t*)&h01; h.y = *(uint32_t*)&h23;
    l.x = *(uint32_t*)&l01; l.y = *(uint32_t*)&l23;
}
static __device__ __forceinline__ uint2 cvt4h(float4 f) {
    __half2 h01 = __floats2half2_rn(f.x, f.y);
    __half2 h23 = __floats2half2_rn(f.z, f.w);
    uint2 h;
    h.x = *(uint32_t*)&h01; h.y = *(uint32_t*)&h23;
    return h;
}

// acts: concat(xctx, x) -> 2-split fp16
#define ACT4   (TT * HID / 4)
#define CTX4   (CTXN * HID / 4)
__global__ __launch_bounds__(256) void cvt_a(
    const float4* __restrict__ xctx, const float4* __restrict__ x,
    uint2* __restrict__ hi, uint2* __restrict__ lo)
{
    int i = blockIdx.x * 256 + threadIdx.x;
    if (i >= ACT4) return;
    float4 f = (i < CTX4) ? xctx[i] : x[i - CTX4];
    uint2 h, l; split4h(f, h, l);
    hi[i] = h; lo[i] = l;
}

// weights -> single rn fp16
#define WQ4 (HID * HID / 4)
#define WK4 (HKV * DH * HID / 4)
__global__ __launch_bounds__(256) void cvt_w(
    const float4* __restrict__ wq, const float4* __restrict__ wk,
    const float4* __restrict__ wv, const float4* __restrict__ wo,
    uint2* __restrict__ oq, uint2* __restrict__ ok,
    uint2* __restrict__ ov, uint2* __restrict__ oo)
{
    long long i = (long long)blockIdx.x * 256 + threadIdx.x;
    const long long s0 = WQ4, s1 = s0 + WK4, s2 = s1 + WK4, s3 = s2 + WQ4;
    if (i >= s3) return;
    const float4* src; uint2* dst; long long j;
    if      (i < s0) { src = wq; dst = oq; j = i; }
    else if (i < s1) { src = wk; dst = ok; j = i - s0; }
    else if (i < s2) { src = wv; dst = ov; j = i - s1; }
    else             { src = wo; dst = oo; j = i - s2; }
    dst[j] = cvt4h(src[j]);
}

__global__ __launch_bounds__(256) void cvt_go(
    const float4* __restrict__ src, uint2* __restrict__ hi,
    uint2* __restrict__ lo, int n4)
{
    int i = blockIdx.x * 256 + threadIdx.x;
    if (i >= n4) return;
    uint2 h, l; split4h(src[i], h, l);
    hi[i] = h; lo[i] = l;
}

// cache region of kc/vc: single rn fp16, pitch-4096 rows
#define CCH4 (HKV * STATE * DH / 4)
__global__ __launch_bounds__(256) void cache_split(
    const float4* __restrict__ cK, const float4* __restrict__ cV,
    uint2* __restrict__ kc, uint2* __restrict__ vc)
{
    int i = blockIdx.x * 256 + threadIdx.x;
    if (i >= 2 * CCH4) return;
    const float4* src = (i < CCH4) ? cK : cV;
    uint2* dst = (i < CCH4) ? kc : vc;
    int j = (i < CCH4) ? i : i - CCH4;
    int e = j * 4;
    int g = e / (STATE * DH);
    int rem = e - g * (STATE * DH);
    int s = rem / DH;
    int d = rem - s * DH;
    size_t di = ((size_t)(g * 4096 + s) * DH + d) / 4;
    dst[di] = cvt4h(src[j]);
}

// ---- split-K combines ----
__global__ __launch_bounds__(256) void add2_k(
    const float4* __restrict__ a, const float4* __restrict__ b,
    float4* __restrict__ o, int n4)
{
    int i = blockIdx.x * 256 + threadIdx.x;
    if (i >= n4) return;
    float4 x = a[i], y = b[i];
    o[i] = make_float4(x.x + y.x, x.y + y.y, x.z + y.z, x.w + y.w);
}
__global__ __launch_bounds__(256) void add4_k(
    const float4* __restrict__ p, float4* __restrict__ o,
    int n4, int stride4)
{
    int i = blockIdx.x * 256 + threadIdx.x;
    if (i >= n4) return;
    float4 a = p[i], b = p[i + stride4];
    float4 c = p[i + 2 * stride4], d = p[i + 3 * stride4];
    o[i] = make_float4((a.x + b.x) + (c.x + d.x),
                       (a.y + b.y) + (c.y + d.y),
                       (a.z + b.z) + (c.z + d.z),
                       (a.w + b.w) + (c.w + d.w));
}

// ==== GEMM v2: C = (Ah+Al)*B^T, 4 warps (2m x 2n), warp tile 32x32 =========
// grid.z = split-K index; C = Cp + z*cstride, koff = z*klen.
#define GP       40
#define ARR_B    5120u
#define STG_B    15360u     // Ah | Al | B
__global__ __launch_bounds__(128) void gemm_f16(
    const __half* __restrict__ aH, const __half* __restrict__ aL,
    const __half* __restrict__ bW,
    float* __restrict__ Cp, size_t cstride, int ldc, int klen)
{
    extern __shared__ __align__(16) char sm[];
    const int tid  = threadIdx.x;
    const int lane = tid & 31;
    const int wid  = tid >> 5;
    const int wm   = wid >> 1;        // 0..1
    const int wn   = wid & 1;         // 0..1
    const int m0   = blockIdx.y * 64;
    const int n0   = blockIdx.x * 64;
    const int z    = blockIdx.z;

    const int NK   = klen / 32;
    const int koff = z * klen;
    float* C = Cp + (size_t)z * cstride;

    const int row = tid >> 1, hf = tid & 1;
    const __half* gaH = aH + (size_t)(m0 + row) * 4096 + koff + hf * 16;
    const __half* gaL = aL + (size_t)(m0 + row) * 4096 + koff + hf * 16;
    const __half* gbW = bW + (size_t)(n0 + row) * 4096 + koff + hf * 16;

    const uint32_t smBase = smem_u32(sm);
    const uint32_t sOff   = (uint32_t)(row * 80 + hf * 32);

    const int mrl = (lane & 7) + ((lane >> 3) & 1) * 8;
    const int kof = ((lane >> 4) & 1) * 8;
    const uint32_t aoff = (uint32_t)(((32 * wm + mrl) * GP + kof) * 2);
    const uint32_t boff = (uint32_t)(((32 * wn + mrl) * GP + kof) * 2);

    float acc[2][4][4];
#pragma unroll
    for (int i = 0; i < 2; i++)
#pragma unroll
        for (int j = 0; j < 4; j++)
#pragma unroll
            for (int e = 0; e < 4; e++) acc[i][j][e] = 0.0f;

#pragma unroll
    for (int p = 0; p < 3; p++) {
        uint32_t d = smBase + (uint32_t)p * STG_B + sOff;
        int k0 = p * 32;
        CPA16(d,                  gaH + k0);
        CPA16(d + 16,             gaH + k0 + 8);
        CPA16(d + ARR_B,          gaL + k0);
        CPA16(d + ARR_B + 16,     gaL + k0 + 8);
        CPA16(d + 2 * ARR_B,      gbW + k0);
        CPA16(d + 2 * ARR_B + 16, gbW + k0 + 8);
        CPA_COMMIT();
    }

    for (int ic = 0; ic < NK; ic++) {
        CPA_WAIT2();
        __syncthreads();

        const uint32_t sb = smBase + (uint32_t)(ic & 3) * STG_B;
#pragma unroll
        for (int ks = 0; ks < 2; ks++) {
            const uint32_t kb = (uint32_t)ks * 32;
            uint32_t Ah[2][4], Al[2][4], B[2][4];
            ldm4(Ah[0], sb + aoff + kb);
            ldm4(Ah[1], sb + aoff + 16 * GP * 2 + kb);
            ldm4(Al[0], sb + ARR_B + aoff + kb);
            ldm4(Al[1], sb + ARR_B + aoff + 16 * GP * 2 + kb);
            ldm4(B[0],  sb + 2 * ARR_B + boff + kb);
            ldm4(B[1],  sb + 2 * ARR_B + boff + 16 * GP * 2 + kb);
#pragma unroll
            for (int tm = 0; tm < 2; tm++)
#pragma unroll
                for (int tn = 0; tn < 4; tn++) {
                    uint32_t b0 = B[tn >> 1][tn & 1];
                    uint32_t b1 = B[tn >> 1][(tn & 1) + 2];
                    mma_f16(acc[tm][tn], Ah[tm], b0, b1);
                    mma_f16(acc[tm][tn], Al[tm], b0, b1);
                }
        }

        if (ic + 3 < NK) {
            int k0 = (ic + 3) * 32;
            uint32_t d = smBase + (uint32_t)((ic + 3) & 3) * STG_B + sOff;
            CPA16(d,                  gaH + k0);
            CPA16(d + 16,             gaH + k0 + 8);
            CPA16(d + ARR_B,          gaL + k0);
            CPA16(d + ARR_B + 16,     gaL + k0 + 8);
            CPA16(d + 2 * ARR_B,      gbW + k0);
            CPA16(d + 2 * ARR_B + 16, gbW + k0 + 8);
        }
        CPA_COMMIT();
    }

    const int r0 = m0 + 32 * wm + (lane >> 2);
    const int c0 = n0 + 32 * wn + (lane & 3) * 2;
#pragma unroll
    for (int tm = 0; tm < 2; tm++)
#pragma unroll
        for (int tn = 0; tn < 4; tn++) {
            float* p = C + (size_t)(r0 + 16 * tm) * ldc + c0 + 8 * tn;
            *(float2*)p = make_float2(acc[tm][tn][0], acc[tm][tn][1]);
            float* p2 = p + (size_t)8 * ldc;
            *(float2*)p2 = make_float2(acc[tm][tn][2], acc[tm][tn][3]);
        }
}

// ---------------- ane-norm + RoPE + scale for Q -> 2-split fp16 --------------
__global__ __launch_bounds__(128) void qnorm_k(
    const float* __restrict__ cq, const float* __restrict__ sq,
    const float* __restrict__ w,
    __half* __restrict__ qrH, __half* __restrict__ qrL)
{
    int h = blockIdx.x, l = blockIdx.y, d = threadIdx.x;
    __shared__ float red[8];
    __shared__ float xs[128];
    float v = g_q[l * HID + h * DH + d];
    float s1 = v, s2 = v * v;
#pragma unroll
    for (int off = 16; off; off >>= 1) {
        s1 += __shfl_down_sync(0xffffffffu, s1, off);
        s2 += __shfl_down_sync(0xffffffffu, s2, off);
    }
    if ((d & 31) == 0) { red[d >> 5] = s1; red[4 + (d >> 5)] = s2; }
    __syncthreads();
    float sum = red[0] + red[1] + red[2] + red[3];
    float sqs = red[4] + red[5] + red[6] + red[7];
    float mean = sum * (1.0f / 128.0f);
    float var  = sqs * (1.0f / 128.0f) - mean * mean;
    float xn = (v - mean) * rsqrtf(var + NEPS) * w[d];
    xs[d] = xn;
    __syncthreads();
    float rot = (d < 64) ? -xs[d + 64] : xs[d - 64];
    float o = (xn * cq[l * DH + d] + rot * sq[l * DH + d]) * SCALE;
    size_t idx = ((size_t)h * LQ + l) * DH + d;
    __half hh = __float2half_rn(o);
    qrH[idx] = hh;
    qrL[idx] = __float2half_rn(o - __half2float(hh));
}

// ---------- ane-norm + RoPE for K; fp32 k/v out + single-fp16 kc/vc ----------
__global__ __launch_bounds__(128) void kvnorm_k(
    const float* __restrict__ ck, const float* __restrict__ sk,
    const float* __restrict__ w,
    float* __restrict__ kOut, float* __restrict__ vOut,
    __half* __restrict__ kc, __half* __restrict__ vc)
{
    int h = blockIdx.x, t = blockIdx.y, d = threadIdx.x;
    __shared__ float red[8];
    __shared__ float xs[128];
    float v = g_k[t * (HKV * DH) + h * DH + d];
    float s1 = v, s2 = v * v;
#pragma unroll
    for (int off = 16; off; off >>= 1) {
        s1 += __shfl_down_sync(0xffffffffu, s1, off);
        s2 += __shfl_down_sync(0xffffffffu, s2, off);
    }
    if ((d & 31) == 0) { red[d >> 5] = s1; red[4 + (d >> 5)] = s2; }
    __syncthreads();
    float sum = red[0] + red[1] + red[2] + red[3];
    float sqs = red[4] + red[5] + red[6] + red[7];
    float mean = sum * (1.0f / 128.0f);
    float var  = sqs * (1.0f / 128.0f) - mean * mean;
    float xn = (v - mean) * rsqrtf(var + NEPS) * w[d];
    xs[d] = xn;
    __syncthreads();
    float rot = (d < 64) ? -xs[d + 64] : xs[d - 64];
    float kv = xn * ck[t * DH + d] + rot * sk[t * DH + d];
    float vv = g_v[t * (HKV * DH) + h * DH + d];
    kOut[((size_t)h * TT + t) * DH + d] = kv;
    vOut[((size_t)h * TT + t) * DH + d] = vv;
    size_t ci = ((size_t)h * 4096 + STATE + t) * DH + d;
    kc[ci] = __float2half_rn(kv);
    vc[ci] = __float2half_rn(vv);
}

// ===== Flash attention: fp16, 2-mma scores / 1-mma PV, split-KV=2 ==========
#define PQB 272u
#define PPB 144u
#define AQH_O 0u
#define AQL_O 8704u
#define ASTG  17408u
#define STGSZ 34816u
#define ASS_O 87040u
#define APH_O 95744u
#define ASM_O 100352u
#define ASL_O 100480u
#define ASC_O 100608u
#define ATTN_SMEM 100736
__global__ __launch_bounds__(256) void attn_mma(
    const __half* __restrict__ qrH, const __half* __restrict__ qrL,
    const __half* __restrict__ kc, const __half* __restrict__ vc,
    float* __restrict__ pO, float* __restrict__ pM, float* __restrict__ pL)
{
    extern __shared__ __align__(16) char sm[];
    const uint32_t base = smem_u32(sm);
    const int tid  = threadIdx.x;
    const int lane = tid & 31;
    const int wid  = tid >> 5;
    const int mw   = wid & 1;
    const int wq   = wid >> 1;
    const int h  = blockIdx.x;
    const int qt = blockIdx.y;
    const int z  = blockIdx.z;
    const int g  = h >> 2;
    const int l0 = qt * 32;

    {
        int r = tid >> 3, c = (tid & 7) * 2;
        const uint4* gh = (const uint4*)(qrH + ((size_t)h * LQ + l0 + r) * DH) + c;
        const uint4* gl = (const uint4*)(qrL + ((size_t)h * LQ + l0 + r) * DH) + c;
        uint4* dh = (uint4*)(sm + AQH_O + r * PQB) + c;
        uint4* dl = (uint4*)(sm + AQL_O + r * PQB) + c;
        dh[0] = gh[0]; dh[1] = gh[1];
        dl[0] = gl[0]; dl[1] = gl[1];
    }
    if (tid < 32) {
        *(float*)(sm + ASM_O + tid * 4) = -1e30f;
        *(float*)(sm + ASL_O + tid * 4) = 0.0f;
    }

    const int fa = tid >> 7, fr = (tid >> 1) & 63, hf = tid & 1;
    const __half* farr = (fa ? vc : kc) + (size_t)(g * 4096 + fr) * DH + hf * 64;
    const uint32_t fdst = base + ASTG + (uint32_t)fa * 17408u +
                          (uint32_t)fr * PQB + (uint32_t)hf * 128u;

    const int ntile = (3968 + l0 + 31) / 64 + 1;
    const int half0 = ntile >> 1;
    const int t0 = z ? half0 : 0;
    const int t1 = z ? ntile : half0;

    {
        const __half* src = farr + (size_t)t0 * 64 * DH;
#pragma unroll
        for (int c = 0; c < 8; c++) CPA16(fdst + c * 16, src + c * 8);
        CPA_COMMIT();
    }

    const uint32_t lmQ = (uint32_t)((16 * mw + (lane & 15)) * PQB + (lane >> 4) * 16);
    const uint32_t lmK = (uint32_t)((16 * wq + (lane & 15)) * PQB + (lane >> 4) * 16);
    const uint32_t lmP = (uint32_t)((16 * mw + (lane & 15)) * PPB + (lane >> 4) * 16);
    const uint32_t lmV = (uint32_t)((lane & 15) * PQB +
                                    (32 * wq + (lane >> 4) * 8) * 2);
    const int r_lo = 16 * mw + (lane >> 2);
    const int r_hi = r_lo + 8;

    float oacc[4][4];
#pragma unroll
    for (int i = 0; i < 4; i++)
#pragma unroll
        for (int e = 0; e < 4; e++) oacc[i][e] = 0.0f;

    for (int t = t0; t < t1; t++) {
        const int tt = t - t0;
        const int st = tt & 1;
        const int s0 = t * 64;
        const uint32_t sg = base + ASTG + (uint32_t)st * STGSZ;

        __syncthreads();
        if (t + 1 < t1) {
            const __half* src = farr + (size_t)(t + 1) * 64 * DH;
            const uint32_t d2 = fdst + (uint32_t)(st ^ 1) * STGSZ;
#pragma unroll
            for (int c = 0; c < 8; c++) CPA16(d2 + c * 16, src + c * 8);
        }
        CPA_COMMIT();
        CPA_WAIT1G();
        __syncthreads();

        float sacc[2][4];
#pragma unroll
        for (int i = 0; i < 2; i++)
#pragma unroll
            for (int e = 0; e < 4; e++) sacc[i][e] = 0.0f;
#pragma unroll
        for (int kt = 0; kt < 8; kt++) {
            uint32_t qh[4], ql[4], kh[4];
            ldm4(qh, base + AQH_O + lmQ + kt * 32);
            ldm4(ql, base + AQL_O + lmQ + kt * 32);
            ldm4(kh, sg + lmK + kt * 32);
#pragma unroll
            for (int nt = 0; nt < 2; nt++) {
                mma_f16(sacc[nt], qh, kh[nt], kh[nt + 2]);
                mma_f16(sacc[nt], ql, kh[nt], kh[nt + 2]);
            }
        }
        {
            int lim_lo = 3968 + l0 + r_lo;
            int lim_hi = lim_lo + 8;
#pragma unroll
            for (int nt = 0; nt < 2; nt++) {
                int c0 = 16 * wq + 8 * nt + (lane & 3) * 2;
                int k0g = s0 + c0;
                float v0 = (k0g     <= lim_lo) ? sacc[nt][0] : -1e30f;
                float v1 = (k0g + 1 <= lim_lo) ? sacc[nt][1] : -1e30f;
                float v2 = (k0g     <= lim_hi) ? sacc[nt][2] : -1e30f;
                float v3 = (k0g + 1 <= lim_hi) ? sacc[nt][3] : -1e30f;
                *(float2*)(sm + ASS_O + r_lo * PQB + c0 * 4) = make_float2(v0, v1);
                *(float2*)(sm + ASS_O + r_hi * PQB + c0 * 4) = make_float2(v2, v3);
            }
        }
        __syncthreads();

        {
            int r = tid >> 3, cg = tid & 7;
            float* rowp = (float*)(sm + ASS_O + r * PQB);
            float4 a = ((float4*)rowp)[cg * 2];
            float4 b = ((float4*)rowp)[cg * 2 + 1];
            float mx = fmaxf(fmaxf(fmaxf(a.x, a.y), fmaxf(a.z, a.w)),
                             fmaxf(fmaxf(b.x, b.y), fmaxf(b.z, b.w)));
#pragma unroll
            for (int o = 1; o < 8; o <<= 1)
                mx = fmaxf(mx, __shfl_xor_sync(0xffffffffu, mx, o));
            float mOld = *(float*)(sm + ASM_O + r * 4);
            mx = fmaxf(mx, mOld);
            float e[8];
            e[0] = __expf(a.x - mx); e[1] = __expf(a.y - mx);
            e[2] = __expf(a.z - mx); e[3] = __expf(a.w - mx);
            e[4] = __expf(b.x - mx); e[5] = __expf(b.y - mx);
            e[6] = __expf(b.z - mx); e[7] = __expf(b.w - mx);
            float s = ((e[0] + e[1]) + (e[2] + e[3])) +
                      ((e[4] + e[5]) + (e[6] + e[7]));
#pragma unroll
            for (int o = 1; o < 8; o <<= 1)
                s += __shfl_xor_sync(0xffffffffu, s, o);
            uint32_t* ph = (uint32_t*)(sm + APH_O + r * PPB) + cg * 4;
#pragma unroll
            for (int j = 0; j < 4; j++) {
                __half2 p = __floats2half2_rn(e[2 * j], e[2 * j + 1]);
                ph[j] = *(uint32_t*)&p;
            }
            if (cg == 0) {
                float c = __expf(mOld - mx);
                *(float*)(sm + ASM_O + r * 4) = mx;
                *(float*)(sm + ASL_O + r * 4) =
                    *(float*)(sm + ASL_O + r * 4) * c + s;
                *(float*)(sm + ASC_O + r * 4) = c;
            }
        }
        __syncthreads();

        {
            float c_lo = *(float*)(sm + ASC_O + r_lo * 4);
            float c_hi = *(float*)(sm + ASC_O + r_hi * 4);
#pragma unroll
            for (int nt = 0; nt < 4; nt++) {
                oacc[nt][0] *= c_lo; oacc[nt][1] *= c_lo;
                oacc[nt][2] *= c_hi; oacc[nt][3] *= c_hi;
            }
        }
        const uint32_t vg = sg + 17408u;
#pragma unroll
        for (int kt = 0; kt < 4; kt++) {
            uint32_t p4[4];
            ldm4(p4, base + APH_O + lmP + kt * 32);
            uint32_t vrow = (uint32_t)(16 * kt) * PQB + lmV;
            uint32_t vh[4];
            ldm4t(vh, vg + vrow);
            mma_f16(oacc[0], p4, vh[0], vh[1]);
            mma_f16(oacc[1], p4, vh[2], vh[3]);
            ldm4t(vh, vg + vrow + 32);
            mma_f16(oacc[2], p4, vh[0], vh[1]);
            mma_f16(oacc[3], p4, vh[2], vh[3]);
        }
    }

    float* oBase = pO + ((size_t)(z * HQ + h) * LQ) * DH;
#pragma unroll
    for (int nt = 0; nt < 4; nt++) {
        int d = 32 * wq + 8 * nt + (lane & 3) * 2;
        *(float2*)(oBase + (size_t)(l0 + r_lo) * DH + d) =
            make_float2(oacc[nt][0], oacc[nt][1]);
        *(float2*)(oBase + (size_t)(l0 + r_hi) * DH + d) =
            make_float2(oacc[nt][2], oacc[nt][3]);
    }
    if (tid < 32) {
        size_t mi = (size_t)(z * HQ + h) * LQ + l0 + tid;
        pM[mi] = *(float*)(sm + ASM_O + tid * 4);
        pL[mi] = *(float*)(sm + ASL_O + tid * 4);
    }
}

// ---- combine the two kv-splits -> g_o ----
__global__ __launch_bounds__(128) void attn_combine(
    const float* __restrict__ pO, const float* __restrict__ pM,
    const float* __restrict__ pL)
{
    int h = blockIdx.x, l = blockIdx.y, d = threadIdx.x;
    size_t i0 = (size_t)h * LQ + l;
    size_t i1 = (size_t)(HQ + h) * LQ + l;
    float m0 = pM[i0], m1 = pM[i1];
    float l0v = pL[i0], l1v = pL[i1];
    float m = fmaxf(m0, m1);
    float e0 = __expf(m0 - m), e1 = __expf(m1 - m);
    float inv = 1.0f / (e0 * l0v + e1 * l1v);
    float o0 = pO[(i0 * DH) + d];
    float o1 = pO[(i1 * DH) + d];
    g_o[(size_t)l * HID + h * DH + d] = (e0 * o0 + e1 * o1) * inv;
}

// ---------------- launch ----------------
extern "C" void kernel_launch(void* const* d_in, const int* in_sizes, int n_in,
                              void* d_out, int out_size) {
    const float* x     = (const float*)d_in[0];
    const float* xctx  = (const float*)d_in[1];
    const float* cosq  = (const float*)d_in[2];
    const float* sinq  = (const float*)d_in[3];
    const float* cosk  = (const float*)d_in[4];
    const float* sink  = (const float*)d_in[5];
    const float* cK    = (const float*)d_in[6];
    const float* cV    = (const float*)d_in[7];
    const float* Wq    = (const float*)d_in[9];
    const float* Wk    = (const float*)d_in[10];
    const float* Wv    = (const float*)d_in[11];
    const float* Wo    = (const float*)d_in[12];
    const float* qw    = (const float*)d_in[13];
    const float* kw    = (const float*)d_in[14];

    float* out  = (float*)d_out;
    float* kOut = out + (size_t)LQ * HID;
    float* vOut = kOut + (size_t)HKV * TT * DH;

    cudaFuncSetAttribute(gemm_f16, cudaFuncAttributeMaxDynamicSharedMemorySize,
                         61440);
    cudaFuncSetAttribute(attn_mma, cudaFuncAttributeMaxDynamicSharedMemorySize,
                         ATTN_SMEM);

    __half *actH, *actL, *wq, *wk, *wv, *wo, *goH, *goL, *qrH, *qrL, *kc, *vc;
    cudaGetSymbolAddress((void**)&actH, c_actH);
    cudaGetSymbolAddress((void**)&actL, c_actL);
    cudaGetSymbolAddress((void**)&wq,   c_wq);
    cudaGetSymbolAddress((void**)&wk,   c_wk);
    cudaGetSymbolAddress((void**)&wv,   c_wv);
    cudaGetSymbolAddress((void**)&wo,   c_wo);
    cudaGetSymbolAddress((void**)&goH,  c_goH);
    cudaGetSymbolAddress((void**)&goL,  c_goL);
    cudaGetSymbolAddress((void**)&qrH,  c_qrH);
    cudaGetSymbolAddress((void**)&qrL,  c_qrL);
    cudaGetSymbolAddress((void**)&kc,   c_kc);
    cudaGetSymbolAddress((void**)&vc,   c_vc);
    float *gq, *go, *gk, *gv, *ps, *aO, *aM, *aL;
    cudaGetSymbolAddress((void**)&gq, g_q);
    cudaGetSymbolAddress((void**)&go, g_o);
    cudaGetSymbolAddress((void**)&gk, g_k);
    cudaGetSymbolAddress((void**)&gv, g_v);
    cudaGetSymbolAddress((void**)&ps, g_ps);
    cudaGetSymbolAddress((void**)&aO, g_aO);
    cudaGetSymbolAddress((void**)&aM, g_aM);
    cudaGetSymbolAddress((void**)&aL, g_aL);

    cache_split<<<(2 * CCH4 + 255) / 256, 256>>>(
        (const float4*)cK, (const float4*)cV, (uint2*)kc, (uint2*)vc);
    cvt_a<<<(ACT4 + 255) / 256, 256>>>((const float4*)xctx, (const float4*)x,
                                       (uint2*)actH, (uint2*)actL);
    {
        long long tot = 2LL * WQ4 + 2LL * WK4;
        cvt_w<<<(unsigned)((tot + 255) / 256), 256>>>(
            (const float4*)Wq, (const float4*)Wk, (const float4*)Wv,
            (const float4*)Wo,
            (uint2*)wq, (uint2*)wk, (uint2*)wv, (uint2*)wo);
    }
    const int NQ4 = LQ * HID / 4;          // 131072
    const int NK4 = TT * HKV * DH / 4;     // 262144
    // q projection: split-K=4
    gemm_f16<<<dim3(64, 2, 4), 128, 61440>>>(
        actH + (size_t)CTXN * HID, actL + (size_t)CTXN * HID, wq,
        ps, (size_t)LQ * HID, HID, 1024);
    add4_k<<<(NQ4 + 255) / 256, 256>>>((const float4*)ps, (float4*)gq,
                                       NQ4, NQ4);
    // k projection: split-K=2
    gemm_f16<<<dim3(16, 16, 2), 128, 61440>>>(
        actH, actL, wk, ps, (size_t)TT * HKV * DH, HKV * DH, 2048);
    add2_k<<<(NK4 + 255) / 256, 256>>>(
        (const float4*)ps, (const float4*)(ps + (size_t)TT * HKV * DH),
        (float4*)gk, NK4);
    // v projection: split-K=2
    gemm_f16<<<dim3(16, 16, 2), 128, 61440>>>(
        actH, actL, wv, ps, (size_t)TT * HKV * DH, HKV * DH, 2048);
    add2_k<<<(NK4 + 255) / 256, 256>>>(
        (const float4*)ps, (const float4*)(ps + (size_t)TT * HKV * DH),
        (float4*)gv, NK4);
    qnorm_k<<<dim3(HQ, LQ), 128>>>(cosq, sinq, qw, qrH, qrL);
    kvnorm_k<<<dim3(HKV, TT), 128>>>(cosk, sink, kw, kOut, vOut, kc, vc);
    // attention: split-KV=2 + combine
    attn_mma<<<dim3(HQ, 4, 2), 256, ATTN_SMEM>>>(qrH, qrL, kc, vc, aO, aM, aL);
    attn_combine<<<dim3(HQ, LQ), 128>>>(aO, aM, aL);
    // output projection: split-K=4
    cvt_go<<<(NQ4 + 255) / 256, 256>>>((const float4*)go,
                                       (uint2*)goH, (uint2*)goL, NQ4);
    gemm_f16<<<dim3(64, 2, 4), 128, 61440>>>(
        goH, goL, wo, ps, (size_t)LQ * HID, HID, 1024);
    add4_k<<<(NQ4 + 255) / 256, 256>>>((const float4*)ps, (float4*)out,
                                       NQ4, NQ4);
}